// round 2
// baseline (speedup 1.0000x reference)
#include <cuda_runtime.h>
#include <cuda_bf16.h>
#include <math.h>

// Problem dims (fixed by reference)
#define BB   128          // batch
#define TT   1024         // tokens
#define HH   512          // hidden
#define AA   256          // attention dim
#define GG   2128         // genes

// ---------------- scratch (no cudaMalloc allowed) ----------------
__device__ float g_gene_proj[BB * AA];   // gene_proj incl. b_genes
__device__ float g_logits[BB * TT];      // pre-softmax energies

// ---------------- helpers ----------------
__device__ __forceinline__ unsigned f2tf32(float f) {
    unsigned u;
    asm("cvt.rna.tf32.f32 %0, %1;" : "=r"(u) : "f"(f));
    return u;
}

__device__ __forceinline__ void mma_tf32(float& d0, float& d1, float& d2, float& d3,
                                         unsigned a0, unsigned a1, unsigned a2, unsigned a3,
                                         unsigned b0, unsigned b1) {
    asm volatile(
        "mma.sync.aligned.m16n8k8.row.col.f32.tf32.tf32.f32 "
        "{%0,%1,%2,%3}, {%4,%5,%6,%7}, {%8,%9}, {%0,%1,%2,%3};\n"
        : "+f"(d0), "+f"(d1), "+f"(d2), "+f"(d3)
        : "r"(a0), "r"(a1), "r"(a2), "r"(a3), "r"(b0), "r"(b1));
}

// ================= Kernel A: gene projection =================
// gene_proj[b][a] = w_num * sum_g genes[b][g] * w_genes[g][a] + b_genes[a]
// grid: 32 blocks (4 batch rows each), 256 threads (one per a)
__global__ __launch_bounds__(256) void gene_proj_kernel(
    const float* __restrict__ genes,
    const float* __restrict__ w_num,
    const float* __restrict__ w_genes,
    const float* __restrict__ b_genes)
{
    __shared__ __align__(16) float gs[4 * GG];   // transposed: gs[g*4 + bb]
    const int tid = threadIdx.x;
    const int b0  = blockIdx.x * 4;

    for (int idx = tid; idx < 4 * GG; idx += 256) {
        int bb = idx / GG;
        int g  = idx - bb * GG;
        gs[g * 4 + bb] = genes[(b0 + bb) * GG + g];
    }
    __syncthreads();

    const int a = tid;
    float acc0 = 0.f, acc1 = 0.f, acc2 = 0.f, acc3 = 0.f;
    #pragma unroll 4
    for (int g = 0; g < GG; g++) {
        float4 gv = *reinterpret_cast<const float4*>(&gs[g * 4]);
        float w = __ldg(&w_genes[g * AA + a]);
        acc0 = fmaf(gv.x, w, acc0);
        acc1 = fmaf(gv.y, w, acc1);
        acc2 = fmaf(gv.z, w, acc2);
        acc3 = fmaf(gv.w, w, acc3);
    }
    const float s  = w_num[0];
    const float bg = b_genes[a];
    g_gene_proj[(b0 + 0) * AA + a] = acc0 * s + bg;
    g_gene_proj[(b0 + 1) * AA + a] = acc1 * s + bg;
    g_gene_proj[(b0 + 2) * AA + a] = acc2 * s + bg;
    g_gene_proj[(b0 + 3) * AA + a] = acc3 * s + bg;
}

// ================= Kernel B: logits (the big GEMM + tanh + v-dot) =================
// Per block: one batch b, 128 tokens. Computes proj[128,256] over K=512 with
// tf32 mma, then logit[t] = sum_a tanh(proj + gene_proj + bias) * v.
// 512 threads = 16 warps in a 4(m) x 4(n) grid; per-warp tile 32x64.
#define KC 16
#define AS_LD 20      // 16 + 4 pad (conflict-free frag loads)
#define BS_LD 264     // 256 + 8 pad (conflict-free frag loads)

__global__ __launch_bounds__(512, 1) void attn_logits_kernel(
    const float* __restrict__ smiles,
    const float* __restrict__ dkernel,
    const float* __restrict__ dbias,
    const float* __restrict__ vvec)
{
    __shared__ __align__(16) unsigned As[128 * AS_LD];
    __shared__ __align__(16) unsigned Bs[KC * BS_LD];
    __shared__ float comb_s[AA];       // gene_proj(b) + dense_bias
    __shared__ float v_s[AA];
    __shared__ float part_s[4 * 128];  // per-n-warp row partials

    const int tid  = threadIdx.x;
    const int lane = tid & 31;
    const int warp = tid >> 5;
    const int g    = lane >> 2;       // group id 0..7
    const int t4   = lane & 3;        // thread-in-group 0..3
    const int wm   = warp & 3;        // warp m index 0..3  (rows wm*32..+31)
    const int wn   = warp >> 2;       // warp n index 0..3  (cols wn*64..+63)

    const int b  = blockIdx.y;
    const int t0 = blockIdx.x * 128;

    if (tid < AA) {
        comb_s[tid] = g_gene_proj[b * AA + tid] + dbias[tid];
        v_s[tid]    = vvec[tid];
    }

    float acc[2][8][4];
    #pragma unroll
    for (int mt = 0; mt < 2; mt++)
        #pragma unroll
        for (int nt = 0; nt < 8; nt++)
            #pragma unroll
            for (int e = 0; e < 4; e++) acc[mt][nt][e] = 0.f;

    const float* smiles_base = smiles + (size_t)b * TT * HH + (size_t)t0 * HH;

    for (int k0 = 0; k0 < HH; k0 += KC) {
        // ---- load A tile: 128 rows x 16 k  (512 float4, 1 per thread) ----
        {
            int r  = tid >> 2;
            int c4 = (tid & 3) * 4;
            float4 f = *reinterpret_cast<const float4*>(smiles_base + r * HH + k0 + c4);
            unsigned* dst = &As[r * AS_LD + c4];
            uint4 u = make_uint4(f2tf32(f.x), f2tf32(f.y), f2tf32(f.z), f2tf32(f.w));
            *reinterpret_cast<uint4*>(dst) = u;
        }
        // ---- load B tile: 16 k x 256 a  (1024 float4, 2 per thread) ----
        #pragma unroll
        for (int i = 0; i < 2; i++) {
            int j  = tid + i * 512;
            int r  = j >> 6;
            int c4 = (j & 63) * 4;
            float4 f = *reinterpret_cast<const float4*>(dkernel + (k0 + r) * AA + c4);
            unsigned* dst = &Bs[r * BS_LD + c4];
            uint4 u = make_uint4(f2tf32(f.x), f2tf32(f.y), f2tf32(f.z), f2tf32(f.w));
            *reinterpret_cast<uint4*>(dst) = u;
        }
        __syncthreads();

        #pragma unroll
        for (int kk = 0; kk < 2; kk++) {
            const int kb = kk * 8;
            unsigned afrag[2][4];
            #pragma unroll
            for (int mt = 0; mt < 2; mt++) {
                int r0 = wm * 32 + mt * 16 + g;
                afrag[mt][0] = As[(r0    ) * AS_LD + kb + t4];
                afrag[mt][1] = As[(r0 + 8) * AS_LD + kb + t4];
                afrag[mt][2] = As[(r0    ) * AS_LD + kb + t4 + 4];
                afrag[mt][3] = As[(r0 + 8) * AS_LD + kb + t4 + 4];
            }
            unsigned bfrag[8][2];
            #pragma unroll
            for (int nt = 0; nt < 8; nt++) {
                int cb = wn * 64 + nt * 8 + g;
                bfrag[nt][0] = Bs[(kb + t4    ) * BS_LD + cb];
                bfrag[nt][1] = Bs[(kb + t4 + 4) * BS_LD + cb];
            }
            #pragma unroll
            for (int mt = 0; mt < 2; mt++)
                #pragma unroll
                for (int nt = 0; nt < 8; nt++)
                    mma_tf32(acc[mt][nt][0], acc[mt][nt][1], acc[mt][nt][2], acc[mt][nt][3],
                             afrag[mt][0], afrag[mt][1], afrag[mt][2], afrag[mt][3],
                             bfrag[nt][0], bfrag[nt][1]);
        }
        __syncthreads();
    }

    // ---- epilogue: tanh + v-dot, deterministic staged reduction ----
    float p[2][2] = {{0.f, 0.f}, {0.f, 0.f}};
    #pragma unroll
    for (int mt = 0; mt < 2; mt++) {
        #pragma unroll
        for (int nt = 0; nt < 8; nt++) {
            int cb2 = wn * 64 + nt * 8 + 2 * t4;
            float add0 = comb_s[cb2],     add1 = comb_s[cb2 + 1];
            float vv0  = v_s[cb2],        vv1  = v_s[cb2 + 1];
            p[mt][0] += tanhf(acc[mt][nt][0] + add0) * vv0
                      + tanhf(acc[mt][nt][1] + add1) * vv1;
            p[mt][1] += tanhf(acc[mt][nt][2] + add0) * vv0
                      + tanhf(acc[mt][nt][3] + add1) * vv1;
        }
    }
    // reduce over the 4 lanes sharing the same rows (t4 = lane bits 0..1)
    #pragma unroll
    for (int mt = 0; mt < 2; mt++) {
        #pragma unroll
        for (int h = 0; h < 2; h++) {
            p[mt][h] += __shfl_xor_sync(0xffffffffu, p[mt][h], 1);
            p[mt][h] += __shfl_xor_sync(0xffffffffu, p[mt][h], 2);
        }
    }
    if (t4 == 0) {
        #pragma unroll
        for (int mt = 0; mt < 2; mt++) {
            int r0 = wm * 32 + mt * 16 + g;
            part_s[wn * 128 + r0]     = p[mt][0];
            part_s[wn * 128 + r0 + 8] = p[mt][1];
        }
    }
    __syncthreads();
    if (tid < 128) {
        float l = part_s[tid] + part_s[128 + tid] + part_s[256 + tid] + part_s[384 + tid];
        g_logits[b * TT + t0 + tid] = l;
    }
}

// ================= Kernel C: softmax over T =================
// one block per batch row; writes alphas directly into d_out[B*H ...]
__global__ __launch_bounds__(256) void softmax_kernel(float* __restrict__ alphas_out)
{
    __shared__ float sl[TT];
    __shared__ float red[256];
    const int tid = threadIdx.x;
    const int b   = blockIdx.x;

    float m = -1e30f;
    #pragma unroll
    for (int i = 0; i < 4; i++) {
        float x = g_logits[b * TT + tid + i * 256];
        sl[tid + i * 256] = x;
        m = fmaxf(m, x);
    }
    red[tid] = m;
    __syncthreads();
    for (int s = 128; s > 0; s >>= 1) {
        if (tid < s) red[tid] = fmaxf(red[tid], red[tid + s]);
        __syncthreads();
    }
    const float mx = red[0];
    __syncthreads();

    float sum = 0.f;
    #pragma unroll
    for (int i = 0; i < 4; i++) {
        float e = expf(sl[tid + i * 256] - mx);
        sl[tid + i * 256] = e;
        sum += e;
    }
    red[tid] = sum;
    __syncthreads();
    for (int s = 128; s > 0; s >>= 1) {
        if (tid < s) red[tid] += red[tid + s];
        __syncthreads();
    }
    const float inv = 1.0f / red[0];
    __syncthreads();

    #pragma unroll
    for (int i = 0; i < 4; i++)
        alphas_out[b * TT + tid + i * 256] = sl[tid + i * 256] * inv;
}

// ================= Kernel D: output = sum_t smiles[b,t,:] * alpha[b,t] =================
// one block per batch row, 512 threads (one per h).
// T-loop unrolled by 4 with independent accumulators -> MLP_p1 >= 4 so the
// DRAM latency (577/MLP) is overlapped (B300 model).
__global__ __launch_bounds__(512) void weighted_sum_kernel(
    const float* __restrict__ smiles,
    const float* __restrict__ alphas,   // d_out + B*H
    float* __restrict__ out)
{
    __shared__ float al[TT];
    const int tid = threadIdx.x;
    const int b   = blockIdx.x;

    al[tid]       = alphas[b * TT + tid];
    al[tid + 512] = alphas[b * TT + tid + 512];
    __syncthreads();

    const float* p = smiles + (size_t)b * TT * HH + tid;
    float a0 = 0.f, a1 = 0.f, a2 = 0.f, a3 = 0.f;
    #pragma unroll 2
    for (int t = 0; t < TT; t += 4) {
        float s0 = p[(size_t)(t + 0) * HH];
        float s1 = p[(size_t)(t + 1) * HH];
        float s2 = p[(size_t)(t + 2) * HH];
        float s3 = p[(size_t)(t + 3) * HH];
        a0 = fmaf(s0, al[t + 0], a0);
        a1 = fmaf(s1, al[t + 1], a1);
        a2 = fmaf(s2, al[t + 2], a2);
        a3 = fmaf(s3, al[t + 3], a3);
    }
    out[b * HH + tid] = (a0 + a1) + (a2 + a3);
}

// ================= launch =================
extern "C" void kernel_launch(void* const* d_in, const int* in_sizes, int n_in,
                              void* d_out, int out_size)
{
    const float* genes   = (const float*)d_in[0];   // [B, G]
    const float* smiles  = (const float*)d_in[1];   // [B, T, H]
    const float* w_num   = (const float*)d_in[2];   // [1]
    const float* w_genes = (const float*)d_in[3];   // [G, A]
    const float* b_genes = (const float*)d_in[4];   // [A]
    const float* dkernel = (const float*)d_in[5];   // [H, A]
    const float* dbias   = (const float*)d_in[6];   // [A]
    const float* vvec    = (const float*)d_in[7];   // [A]

    float* out    = (float*)d_out;                  // [B, H] at offset 0
    float* alphas = out + BB * HH;                  // [B, T] after output

    gene_proj_kernel<<<32, 256>>>(genes, w_num, w_genes, b_genes);
    attn_logits_kernel<<<dim3(TT / 128, BB), 512>>>(smiles, dkernel, dbias, vvec);
    softmax_kernel<<<BB, 256>>>(alphas);
    weighted_sum_kernel<<<BB, 512>>>(smiles, alphas, out);
}

// round 4
// speedup vs baseline: 1.4617x; 1.4617x over previous
#include <cuda_runtime.h>
#include <cuda_fp16.h>
#include <stdint.h>
#include <math.h>

// Problem dims (fixed by reference)
#define BB   128          // batch
#define TT   1024         // tokens
#define HH   512          // hidden
#define AA   256          // attention dim
#define GG   2128         // genes

#define NSTAGE 16         // K stages
#define KC     32         // K per stage
#define LDA    20         // A smem row stride in b32 words (16 data + 4 pad)
#define LDB    20         // B smem row stride in b32 words
#define WS_SPLIT 8

// ---------------- scratch (no cudaMalloc allowed) ----------------
__device__ float    g_gene_proj[BB * AA];            // gene_proj incl. b_genes
__device__ float    g_logits[BB * TT];               // pre-softmax energies
__device__ __align__(16) unsigned g_bh[NSTAGE * AA * (KC / 2)]; // dkernel^T fp16, [stage][a][16 words]
__device__ float    g_part[WS_SPLIT * BB * HH];      // weighted-sum partials

// ---------------- helpers ----------------
__device__ __forceinline__ unsigned packh2(float a, float b) {
    __half2 h = __floats2half2_rn(a, b);              // low = a, high = b
    return *reinterpret_cast<unsigned*>(&h);
}
__device__ __forceinline__ uint32_t s2u(const void* p) {
    uint32_t a;
    asm("{ .reg .u64 t; cvta.to.shared.u64 t, %1; cvt.u32.u64 %0, t; }" : "=r"(a) : "l"(p));
    return a;
}
__device__ __forceinline__ void cp16(uint32_t d, const void* s) {
    asm volatile("cp.async.cg.shared.global [%0], [%1], 16;" :: "r"(d), "l"(s) : "memory");
}
__device__ __forceinline__ void mma_f16(float& d0, float& d1, float& d2, float& d3,
                                        unsigned a0, unsigned a1, unsigned a2, unsigned a3,
                                        unsigned b0, unsigned b1) {
    asm volatile(
        "mma.sync.aligned.m16n8k16.row.col.f32.f16.f16.f32 "
        "{%0,%1,%2,%3}, {%4,%5,%6,%7}, {%8,%9}, {%0,%1,%2,%3};\n"
        : "+f"(d0), "+f"(d1), "+f"(d2), "+f"(d3)
        : "r"(a0), "r"(a1), "r"(a2), "r"(a3), "r"(b0), "r"(b1));
}

// ================= Kernel A: gene projection =================
__global__ __launch_bounds__(256) void gene_proj_kernel(
    const float* __restrict__ genes,
    const float* __restrict__ w_num,
    const float* __restrict__ w_genes,
    const float* __restrict__ b_genes)
{
    __shared__ __align__(16) float gs[4 * GG];
    const int tid = threadIdx.x;
    const int b0  = blockIdx.x * 4;

    for (int idx = tid; idx < 4 * GG; idx += 256) {
        int bb = idx / GG;
        int g  = idx - bb * GG;
        gs[g * 4 + bb] = genes[(b0 + bb) * GG + g];
    }
    __syncthreads();

    const int a = tid;
    float acc0 = 0.f, acc1 = 0.f, acc2 = 0.f, acc3 = 0.f;
    #pragma unroll 4
    for (int g = 0; g < GG; g++) {
        float4 gv = *reinterpret_cast<const float4*>(&gs[g * 4]);
        float w = __ldg(&w_genes[g * AA + a]);
        acc0 = fmaf(gv.x, w, acc0);
        acc1 = fmaf(gv.y, w, acc1);
        acc2 = fmaf(gv.z, w, acc2);
        acc3 = fmaf(gv.w, w, acc3);
    }
    const float s  = w_num[0];
    const float bg = b_genes[a];
    g_gene_proj[(b0 + 0) * AA + a] = acc0 * s + bg;
    g_gene_proj[(b0 + 1) * AA + a] = acc1 * s + bg;
    g_gene_proj[(b0 + 2) * AA + a] = acc2 * s + bg;
    g_gene_proj[(b0 + 3) * AA + a] = acc3 * s + bg;
}

// ================= Kernel W: prep B (dkernel^T -> fp16, stage-blocked) =================
// g_bh[s][a][j] = half2(dk[s*32+2j][a], dk[s*32+2j+1][a]). grid=16, 256 thr.
__global__ __launch_bounds__(256) void prep_bhalf(const float* __restrict__ dk)
{
    const int s = blockIdx.x;
    const int a = threadIdx.x;
    unsigned w[16];
    #pragma unroll
    for (int j = 0; j < 16; j++) {
        float f0 = dk[(size_t)(s * KC + 2 * j)     * AA + a];
        float f1 = dk[(size_t)(s * KC + 2 * j + 1) * AA + a];
        w[j] = packh2(f0, f1);
    }
    uint4* dst = reinterpret_cast<uint4*>(g_bh + ((size_t)s * AA + a) * 16);
    dst[0] = make_uint4(w[0],  w[1],  w[2],  w[3]);
    dst[1] = make_uint4(w[4],  w[5],  w[6],  w[7]);
    dst[2] = make_uint4(w[8],  w[9],  w[10], w[11]);
    dst[3] = make_uint4(w[12], w[13], w[14], w[15]);
}

// ================= Kernel B: logits via fp16 mma.sync + cp.async pipeline =================
// smem word layout (dynamic, 16384 words = 64KB):
//   As[buf] at buf*2560 (128 rows x LDA)
//   Bs[buf] at 5120 + buf*5120 (256 rows x LDB)
//   comb @15360, v @15616, part @15872
#define CPB(u) do {                                                              \
    int _buf = (u) & 1;                                                          \
    const char* _s = (const char*)g_bh + (size_t)(u) * 16384;                    \
    uint32_t _d = smb + (5120u + (unsigned)_buf * 5120u) * 4u;                   \
    _Pragma("unroll")                                                            \
    for (int _i = 0; _i < 2; _i++) {                                             \
        int _q = tid + _i * 512;                                                 \
        int _row = _q >> 2, _c = _q & 3;                                         \
        cp16(_d + _row * 80 + _c * 16, _s + _row * 64 + _c * 16);                \
    }                                                                            \
    asm volatile("cp.async.commit_group;" ::: "memory");                         \
} while (0)

#define LDA_G(u, dst) do {                                                       \
    const float* _p = Ag + (size_t)r * HH + (u) * KC + c4 * 8;                   \
    float4 _f0 = *(const float4*)_p;                                             \
    float4 _f1 = *(const float4*)(_p + 4);                                       \
    dst[0] = packh2(_f0.x, _f0.y); dst[1] = packh2(_f0.z, _f0.w);                \
    dst[2] = packh2(_f1.x, _f1.y); dst[3] = packh2(_f1.z, _f1.w);                \
} while (0)

#define STA(buf, src) do {                                                       \
    unsigned* _d = smw + (buf) * 2560 + r * LDA + c4 * 4;                        \
    *(uint4*)_d = make_uint4(src[0], src[1], src[2], src[3]);                    \
} while (0)

__global__ __launch_bounds__(512, 1) void attn_logits_f16k(
    const float* __restrict__ smiles,
    const float* __restrict__ dbias,
    const float* __restrict__ vvec)
{
    extern __shared__ __align__(16) float sm[];
    unsigned* smw  = (unsigned*)sm;
    float*    comb = sm + 15360;
    float*    vsh  = sm + 15616;
    float*    part = sm + 15872;

    const int tid  = threadIdx.x;
    const int lane = tid & 31;
    const int warp = tid >> 5;
    const int g    = lane >> 2;
    const int t4   = lane & 3;
    const int wm   = warp & 3;
    const int wn   = warp >> 2;
    const int b    = blockIdx.y;
    const int t0   = blockIdx.x * 128;

    if (tid < AA) {
        comb[tid] = g_gene_proj[b * AA + tid] + dbias[tid];
        vsh[tid]  = vvec[tid];
    }

    const float* Ag = smiles + ((size_t)b * TT + t0) * HH;
    const int r  = tid >> 2;
    const int c4 = tid & 3;
    const uint32_t smb = s2u(sm);

    float acc[2][8][4];
    #pragma unroll
    for (int mt = 0; mt < 2; mt++)
        #pragma unroll
        for (int nt = 0; nt < 8; nt++)
            #pragma unroll
            for (int e = 0; e < 4; e++) acc[mt][nt][e] = 0.f;

    unsigned aCur[4], aPre[4];
    CPB(0);
    LDA_G(0, aCur);
    STA(0, aCur);
    LDA_G(1, aPre);
    asm volatile("cp.async.wait_group 0;" ::: "memory");
    __syncthreads();

    #pragma unroll 2
    for (int u = 0; u < NSTAGE; u++) {
        const int buf = u & 1;
        if (u < NSTAGE - 1) CPB(u + 1);

        const unsigned* As = smw + buf * 2560;
        const unsigned* Bs = smw + 5120 + buf * 5120;

        #pragma unroll
        for (int kk = 0; kk < 2; kk++) {
            unsigned bf0[8], bf1[8];
            #pragma unroll
            for (int nt = 0; nt < 8; nt++) {
                int n = wn * 64 + nt * 8 + g;
                bf0[nt] = Bs[n * LDB + kk * 8 + t4];
                bf1[nt] = Bs[n * LDB + kk * 8 + t4 + 4];
            }
            #pragma unroll
            for (int mt = 0; mt < 2; mt++) {
                int r0 = wm * 32 + mt * 16 + g;
                unsigned a0 = As[(r0    ) * LDA + kk * 8 + t4];
                unsigned a1 = As[(r0 + 8) * LDA + kk * 8 + t4];
                unsigned a2 = As[(r0    ) * LDA + kk * 8 + t4 + 4];
                unsigned a3 = As[(r0 + 8) * LDA + kk * 8 + t4 + 4];
                #pragma unroll
                for (int nt = 0; nt < 8; nt++)
                    mma_f16(acc[mt][nt][0], acc[mt][nt][1], acc[mt][nt][2], acc[mt][nt][3],
                            a0, a1, a2, a3, bf0[nt], bf1[nt]);
            }
        }

        if (u < NSTAGE - 1) STA(buf ^ 1, aPre);
        if (u < NSTAGE - 2) LDA_G(u + 2, aPre);
        if (u < NSTAGE - 1) asm volatile("cp.async.wait_group 0;" ::: "memory");
        __syncthreads();
    }

    // ---- epilogue: tanh + v-dot, deterministic staged reduction ----
    float pe[2][2] = {{0.f, 0.f}, {0.f, 0.f}};
    #pragma unroll
    for (int mt = 0; mt < 2; mt++) {
        #pragma unroll
        for (int nt = 0; nt < 8; nt++) {
            int cb2 = wn * 64 + nt * 8 + 2 * t4;
            float add0 = comb[cb2],     add1 = comb[cb2 + 1];
            float vv0  = vsh[cb2],      vv1  = vsh[cb2 + 1];
            pe[mt][0] += tanhf(acc[mt][nt][0] + add0) * vv0
                       + tanhf(acc[mt][nt][1] + add1) * vv1;
            pe[mt][1] += tanhf(acc[mt][nt][2] + add0) * vv0
                       + tanhf(acc[mt][nt][3] + add1) * vv1;
        }
    }
    #pragma unroll
    for (int mt = 0; mt < 2; mt++) {
        #pragma unroll
        for (int h = 0; h < 2; h++) {
            pe[mt][h] += __shfl_xor_sync(0xffffffffu, pe[mt][h], 1);
            pe[mt][h] += __shfl_xor_sync(0xffffffffu, pe[mt][h], 2);
        }
    }
    if (t4 == 0) {
        #pragma unroll
        for (int mt = 0; mt < 2; mt++) {
            int r0 = wm * 32 + mt * 16 + g;
            part[wn * 128 + r0]     = pe[mt][0];
            part[wn * 128 + r0 + 8] = pe[mt][1];
        }
    }
    __syncthreads();
    if (tid < 128) {
        g_logits[b * TT + t0 + tid] =
            part[tid] + part[128 + tid] + part[256 + tid] + part[384 + tid];
    }
}

// ================= Kernel C: softmax over T =================
__global__ __launch_bounds__(256) void softmax_kernel(float* __restrict__ alphas_out)
{
    __shared__ float sl[TT];
    __shared__ float red[256];
    const int tid = threadIdx.x;
    const int b   = blockIdx.x;

    float m = -1e30f;
    #pragma unroll
    for (int i = 0; i < 4; i++) {
        float x = g_logits[b * TT + tid + i * 256];
        sl[tid + i * 256] = x;
        m = fmaxf(m, x);
    }
    red[tid] = m;
    __syncthreads();
    for (int s = 128; s > 0; s >>= 1) {
        if (tid < s) red[tid] = fmaxf(red[tid], red[tid + s]);
        __syncthreads();
    }
    const float mx = red[0];
    __syncthreads();

    float sum = 0.f;
    #pragma unroll
    for (int i = 0; i < 4; i++) {
        float e = expf(sl[tid + i * 256] - mx);
        sl[tid + i * 256] = e;
        sum += e;
    }
    red[tid] = sum;
    __syncthreads();
    for (int s = 128; s > 0; s >>= 1) {
        if (tid < s) red[tid] += red[tid + s];
        __syncthreads();
    }
    const float inv = 1.0f / red[0];
    __syncthreads();

    #pragma unroll
    for (int i = 0; i < 4; i++)
        alphas_out[b * TT + tid + i * 256] = sl[tid + i * 256] * inv;
}

// ================= Kernel D1: weighted-sum partials (T split 8-ways) =================
__global__ __launch_bounds__(128) void wsum_part(
    const float* __restrict__ smiles,
    const float* __restrict__ alphas)
{
    __shared__ float al[128];
    const int tid = threadIdx.x;
    const int b   = blockIdx.x;
    const int c   = blockIdx.y;

    al[tid] = alphas[b * TT + c * 128 + tid];
    __syncthreads();

    const float4* sp = reinterpret_cast<const float4*>(
        smiles + ((size_t)b * TT + (size_t)c * 128) * HH) + tid;

    float4 a0 = {0,0,0,0}, a1 = {0,0,0,0}, a2 = {0,0,0,0}, a3 = {0,0,0,0};
    #pragma unroll 2
    for (int t = 0; t < 128; t += 4) {
        float4 s0 = sp[(size_t)(t + 0) * 128];
        float4 s1 = sp[(size_t)(t + 1) * 128];
        float4 s2 = sp[(size_t)(t + 2) * 128];
        float4 s3 = sp[(size_t)(t + 3) * 128];
        float w0 = al[t], w1 = al[t + 1], w2 = al[t + 2], w3 = al[t + 3];
        a0.x = fmaf(s0.x, w0, a0.x); a0.y = fmaf(s0.y, w0, a0.y);
        a0.z = fmaf(s0.z, w0, a0.z); a0.w = fmaf(s0.w, w0, a0.w);
        a1.x = fmaf(s1.x, w1, a1.x); a1.y = fmaf(s1.y, w1, a1.y);
        a1.z = fmaf(s1.z, w1, a1.z); a1.w = fmaf(s1.w, w1, a1.w);
        a2.x = fmaf(s2.x, w2, a2.x); a2.y = fmaf(s2.y, w2, a2.y);
        a2.z = fmaf(s2.z, w2, a2.z); a2.w = fmaf(s2.w, w2, a2.w);
        a3.x = fmaf(s3.x, w3, a3.x); a3.y = fmaf(s3.y, w3, a3.y);
        a3.z = fmaf(s3.z, w3, a3.z); a3.w = fmaf(s3.w, w3, a3.w);
    }
    float4 out;
    out.x = (a0.x + a1.x) + (a2.x + a3.x);
    out.y = (a0.y + a1.y) + (a2.y + a3.y);
    out.z = (a0.z + a1.z) + (a2.z + a3.z);
    out.w = (a0.w + a1.w) + (a2.w + a3.w);
    *reinterpret_cast<float4*>(&g_part[((size_t)c * BB + b) * HH + tid * 4]) = out;
}

// ================= Kernel D2: reduce partials =================
__global__ __launch_bounds__(256) void wsum_reduce(float* __restrict__ out)
{
    const int i = blockIdx.x * 256 + threadIdx.x;
    float s = 0.f;
    #pragma unroll
    for (int c = 0; c < WS_SPLIT; c++) s += g_part[(size_t)c * BB * HH + i];
    out[i] = s;
}

// ================= launch =================
extern "C" void kernel_launch(void* const* d_in, const int* in_sizes, int n_in,
                              void* d_out, int out_size)
{
    const float* genes   = (const float*)d_in[0];   // [B, G]
    const float* smiles  = (const float*)d_in[1];   // [B, T, H]
    const float* w_num   = (const float*)d_in[2];   // [1]
    const float* w_genes = (const float*)d_in[3];   // [G, A]
    const float* b_genes = (const float*)d_in[4];   // [A]
    const float* dkernel = (const float*)d_in[5];   // [H, A]
    const float* dbias   = (const float*)d_in[6];   // [A]
    const float* vvec    = (const float*)d_in[7];   // [A]

    float* out    = (float*)d_out;                  // [B, H] at offset 0
    float* alphas = out + BB * HH;                  // [B, T] after output

    cudaFuncSetAttribute(attn_logits_f16k, cudaFuncAttributeMaxDynamicSharedMemorySize, 65536);

    gene_proj_kernel<<<32, 256>>>(genes, w_num, w_genes, b_genes);
    prep_bhalf<<<NSTAGE, 256>>>(dkernel);
    attn_logits_f16k<<<dim3(TT / 128, BB), 512, 65536>>>(smiles, dbias, vvec);
    softmax_kernel<<<BB, 256>>>(alphas);
    wsum_part<<<dim3(BB, WS_SPLIT), 128>>>(smiles, alphas);
    wsum_reduce<<<BB * HH / 256, 256>>>(out);
}

// round 5
// speedup vs baseline: 2.4785x; 1.6956x over previous
#include <cuda_runtime.h>
#include <cuda_fp16.h>
#include <stdint.h>
#include <math.h>

// Problem dims (fixed by reference)
#define BB   128          // batch
#define TT   1024         // tokens
#define HH   512          // hidden
#define AA   256          // attention dim
#define GG   2128         // genes

#define NSTAGE 16         // K stages
#define KC     32         // K per stage
#define LDA    20         // A smem row stride in b32 words (16 data + 4 pad)
#define LDB    20         // B smem row stride in b32 words
#define WS_SPLIT 8
#define GCHUNK 266        // GG / 8

// ---------------- scratch (no cudaMalloc allowed) ----------------
__device__ float    g_gene_proj[BB * AA];            // gene_proj incl. b_genes
__device__ float    g_gp_part[8 * BB * AA];          // gene partials
__device__ float    g_logits[BB * TT];               // pre-softmax energies
__device__ __align__(16) unsigned g_bh[NSTAGE * AA * (KC / 2)]; // dkernel^T fp16, [stage][a][16 words]
__device__ float    g_part[WS_SPLIT * BB * HH];      // weighted-sum partials

// ---------------- helpers ----------------
__device__ __forceinline__ unsigned packh2(float a, float b) {
    __half2 h = __floats2half2_rn(a, b);              // low = a, high = b
    return *reinterpret_cast<unsigned*>(&h);
}
__device__ __forceinline__ uint32_t s2u(const void* p) {
    uint32_t a;
    asm("{ .reg .u64 t; cvta.to.shared.u64 t, %1; cvt.u32.u64 %0, t; }" : "=r"(a) : "l"(p));
    return a;
}
__device__ __forceinline__ void cp16(uint32_t d, const void* s) {
    asm volatile("cp.async.cg.shared.global [%0], [%1], 16;" :: "r"(d), "l"(s) : "memory");
}
__device__ __forceinline__ void ldmat4(unsigned* r, uint32_t addr) {
    asm volatile("ldmatrix.sync.aligned.m8n8.x4.shared.b16 {%0,%1,%2,%3}, [%4];"
                 : "=r"(r[0]), "=r"(r[1]), "=r"(r[2]), "=r"(r[3]) : "r"(addr));
}
__device__ __forceinline__ void mma_f16(float& d0, float& d1, float& d2, float& d3,
                                        unsigned a0, unsigned a1, unsigned a2, unsigned a3,
                                        unsigned b0, unsigned b1) {
    asm volatile(
        "mma.sync.aligned.m16n8k16.row.col.f32.f16.f16.f32 "
        "{%0,%1,%2,%3}, {%4,%5,%6,%7}, {%8,%9}, {%0,%1,%2,%3};\n"
        : "+f"(d0), "+f"(d1), "+f"(d2), "+f"(d3)
        : "r"(a0), "r"(a1), "r"(a2), "r"(a3), "r"(b0), "r"(b1));
}

// ================= Kernel A1: gene projection partials (G split 8-way) =================
// grid (32 b-groups, 8 g-chunks), 256 threads (one per a)
__global__ __launch_bounds__(256) void gene_proj_part(
    const float* __restrict__ genes,
    const float* __restrict__ w_genes)
{
    __shared__ __align__(16) float gs[4 * GCHUNK];   // transposed: gs[g*4 + bb]
    const int tid = threadIdx.x;
    const int b0  = blockIdx.x * 4;
    const int g0  = blockIdx.y * GCHUNK;

    for (int idx = tid; idx < 4 * GCHUNK; idx += 256) {
        int bb = idx / GCHUNK;
        int g  = idx - bb * GCHUNK;
        gs[g * 4 + bb] = genes[(b0 + bb) * GG + g0 + g];
    }
    __syncthreads();

    const int a = tid;
    float acc0 = 0.f, acc1 = 0.f, acc2 = 0.f, acc3 = 0.f;
    #pragma unroll 2
    for (int g = 0; g < GCHUNK; g++) {
        float4 gv = *reinterpret_cast<const float4*>(&gs[g * 4]);
        float w = __ldg(&w_genes[(size_t)(g0 + g) * AA + a]);
        acc0 = fmaf(gv.x, w, acc0);
        acc1 = fmaf(gv.y, w, acc1);
        acc2 = fmaf(gv.z, w, acc2);
        acc3 = fmaf(gv.w, w, acc3);
    }
    float* dst = g_gp_part + ((size_t)blockIdx.y * BB + b0) * AA + a;
    dst[0 * AA] = acc0;
    dst[1 * AA] = acc1;
    dst[2 * AA] = acc2;
    dst[3 * AA] = acc3;
}

// ================= Kernel A2: reduce gene partials =================
__global__ __launch_bounds__(256) void gene_proj_reduce(
    const float* __restrict__ w_num,
    const float* __restrict__ b_genes)
{
    const int b = blockIdx.x;
    const int a = threadIdx.x;
    float s = 0.f;
    #pragma unroll
    for (int c = 0; c < 8; c++) s += g_gp_part[((size_t)c * BB + b) * AA + a];
    g_gene_proj[b * AA + a] = s * w_num[0] + b_genes[a];
}

// ================= Kernel W: prep B (dkernel^T -> fp16, stage-blocked) =================
__global__ __launch_bounds__(256) void prep_bhalf(const float* __restrict__ dk)
{
    const int s = blockIdx.x;
    const int a = threadIdx.x;
    unsigned w[16];
    #pragma unroll
    for (int j = 0; j < 16; j++) {
        float f0 = dk[(size_t)(s * KC + 2 * j)     * AA + a];
        float f1 = dk[(size_t)(s * KC + 2 * j + 1) * AA + a];
        w[j] = packh2(f0, f1);
    }
    uint4* dst = reinterpret_cast<uint4*>(g_bh + ((size_t)s * AA + a) * 16);
    dst[0] = make_uint4(w[0],  w[1],  w[2],  w[3]);
    dst[1] = make_uint4(w[4],  w[5],  w[6],  w[7]);
    dst[2] = make_uint4(w[8],  w[9],  w[10], w[11]);
    dst[3] = make_uint4(w[12], w[13], w[14], w[15]);
}

// ================= Kernel B: logits via fp16 mma.sync + cp.async + ldmatrix =================
// smem word layout (dynamic, 16384 words = 64KB):
//   As[buf] at buf*2560 (128 rows x LDA), Bs[buf] at 5120 + buf*5120 (256 rows x LDB)
//   comb @15360, v @15616, part @15872
#define CPB(u) do {                                                              \
    int _buf = (u) & 1;                                                          \
    const char* _s = (const char*)g_bh + (size_t)(u) * 16384;                    \
    uint32_t _d = smb + (5120u + (unsigned)_buf * 5120u) * 4u;                   \
    _Pragma("unroll")                                                            \
    for (int _i = 0; _i < 2; _i++) {                                             \
        int _q = tid + _i * 512;                                                 \
        int _row = _q >> 2, _c = _q & 3;                                         \
        cp16(_d + _row * 80 + _c * 16, _s + _row * 64 + _c * 16);                \
    }                                                                            \
    asm volatile("cp.async.commit_group;" ::: "memory");                         \
} while (0)

#define LDA_G(u, dst) do {                                                       \
    const float* _p = Ag + (size_t)r * HH + (u) * KC + c4 * 8;                   \
    float4 _f0 = *(const float4*)_p;                                             \
    float4 _f1 = *(const float4*)(_p + 4);                                       \
    dst[0] = packh2(_f0.x, _f0.y); dst[1] = packh2(_f0.z, _f0.w);                \
    dst[2] = packh2(_f1.x, _f1.y); dst[3] = packh2(_f1.z, _f1.w);                \
} while (0)

#define STA(buf, src) do {                                                       \
    unsigned* _d = smw + (buf) * 2560 + r * LDA + c4 * 4;                        \
    *(uint4*)_d = make_uint4(src[0], src[1], src[2], src[3]);                    \
} while (0)

__global__ __launch_bounds__(512, 1) void attn_logits_f16k(
    const float* __restrict__ smiles,
    const float* __restrict__ dbias,
    const float* __restrict__ vvec)
{
    extern __shared__ __align__(16) float sm[];
    unsigned* smw  = (unsigned*)sm;
    float*    comb = sm + 15360;
    float*    vsh  = sm + 15616;
    float*    part = sm + 15872;

    const int tid  = threadIdx.x;
    const int lane = tid & 31;
    const int warp = tid >> 5;
    const int g    = lane >> 2;
    const int t4   = lane & 3;
    const int wm   = warp & 3;
    const int wn   = warp >> 2;
    const int b    = blockIdx.y;
    const int t0   = blockIdx.x * 128;

    if (tid < AA) {
        comb[tid] = g_gene_proj[b * AA + tid] + dbias[tid];
        vsh[tid]  = vvec[tid];
    }

    const float* Ag = smiles + ((size_t)b * TT + t0) * HH;
    const int r  = tid >> 2;
    const int c4 = tid & 3;
    const uint32_t smb = s2u(sm);

    // ldmatrix lane-dependent byte offsets (within a buffer)
    const uint32_t aoff0 = (uint32_t)(((wm * 32 + (lane & 15)) * LDA + ((lane & 16) ? 4 : 0)) * 4);
    const uint32_t aoff1 = aoff0 + 16u * LDA * 4u;
    uint32_t boff[4];
    #pragma unroll
    for (int j = 0; j < 4; j++)
        boff[j] = (uint32_t)(((wn * 64 + j * 16 + (lane & 7) + ((lane & 16) ? 8 : 0)) * LDB
                              + ((lane & 8) ? 4 : 0)) * 4);

    float acc[2][8][4];
    #pragma unroll
    for (int mt = 0; mt < 2; mt++)
        #pragma unroll
        for (int nt = 0; nt < 8; nt++)
            #pragma unroll
            for (int e = 0; e < 4; e++) acc[mt][nt][e] = 0.f;

    unsigned aCur[4], aPre[4];
    CPB(0);
    LDA_G(0, aCur);
    STA(0, aCur);
    LDA_G(1, aPre);
    asm volatile("cp.async.wait_group 0;" ::: "memory");
    __syncthreads();

    #pragma unroll 2
    for (int u = 0; u < NSTAGE; u++) {
        const int buf = u & 1;
        if (u < NSTAGE - 1) CPB(u + 1);

        const uint32_t abase = smb + (uint32_t)buf * 2560u * 4u;
        const uint32_t bbase = smb + (5120u + (uint32_t)buf * 5120u) * 4u;

        #pragma unroll
        for (int kk = 0; kk < 2; kk++) {
            const uint32_t ko = (uint32_t)kk * 32u;
            unsigned af[2][4];
            ldmat4(af[0], abase + aoff0 + ko);
            ldmat4(af[1], abase + aoff1 + ko);
            #pragma unroll
            for (int j = 0; j < 4; j++) {
                unsigned bf[4];
                ldmat4(bf, bbase + boff[j] + ko);
                #pragma unroll
                for (int mt = 0; mt < 2; mt++) {
                    mma_f16(acc[mt][2*j][0],   acc[mt][2*j][1],   acc[mt][2*j][2],   acc[mt][2*j][3],
                            af[mt][0], af[mt][1], af[mt][2], af[mt][3], bf[0], bf[1]);
                    mma_f16(acc[mt][2*j+1][0], acc[mt][2*j+1][1], acc[mt][2*j+1][2], acc[mt][2*j+1][3],
                            af[mt][0], af[mt][1], af[mt][2], af[mt][3], bf[2], bf[3]);
                }
            }
        }

        if (u < NSTAGE - 1) STA(buf ^ 1, aPre);
        if (u < NSTAGE - 2) LDA_G(u + 2, aPre);
        if (u < NSTAGE - 1) asm volatile("cp.async.wait_group 0;" ::: "memory");
        __syncthreads();
    }

    // ---- epilogue: tanh + v-dot, deterministic staged reduction ----
    float pe[2][2] = {{0.f, 0.f}, {0.f, 0.f}};
    #pragma unroll
    for (int mt = 0; mt < 2; mt++) {
        #pragma unroll
        for (int nt = 0; nt < 8; nt++) {
            int cb2 = wn * 64 + nt * 8 + 2 * t4;
            float add0 = comb[cb2],     add1 = comb[cb2 + 1];
            float vv0  = vsh[cb2],      vv1  = vsh[cb2 + 1];
            pe[mt][0] += tanhf(acc[mt][nt][0] + add0) * vv0
                       + tanhf(acc[mt][nt][1] + add1) * vv1;
            pe[mt][1] += tanhf(acc[mt][nt][2] + add0) * vv0
                       + tanhf(acc[mt][nt][3] + add1) * vv1;
        }
    }
    #pragma unroll
    for (int mt = 0; mt < 2; mt++) {
        #pragma unroll
        for (int h = 0; h < 2; h++) {
            pe[mt][h] += __shfl_xor_sync(0xffffffffu, pe[mt][h], 1);
            pe[mt][h] += __shfl_xor_sync(0xffffffffu, pe[mt][h], 2);
        }
    }
    if (t4 == 0) {
        #pragma unroll
        for (int mt = 0; mt < 2; mt++) {
            int r0 = wm * 32 + mt * 16 + g;
            part[wn * 128 + r0]     = pe[mt][0];
            part[wn * 128 + r0 + 8] = pe[mt][1];
        }
    }
    __syncthreads();
    if (tid < 128) {
        g_logits[b * TT + t0 + tid] =
            part[tid] + part[128 + tid] + part[256 + tid] + part[384 + tid];
    }
}

// ================= Kernel C: softmax over T =================
__global__ __launch_bounds__(256) void softmax_kernel(float* __restrict__ alphas_out)
{
    __shared__ float sl[TT];
    __shared__ float red[256];
    const int tid = threadIdx.x;
    const int b   = blockIdx.x;

    float m = -1e30f;
    #pragma unroll
    for (int i = 0; i < 4; i++) {
        float x = g_logits[b * TT + tid + i * 256];
        sl[tid + i * 256] = x;
        m = fmaxf(m, x);
    }
    red[tid] = m;
    __syncthreads();
    for (int s = 128; s > 0; s >>= 1) {
        if (tid < s) red[tid] = fmaxf(red[tid], red[tid + s]);
        __syncthreads();
    }
    const float mx = red[0];
    __syncthreads();

    float sum = 0.f;
    #pragma unroll
    for (int i = 0; i < 4; i++) {
        float e = expf(sl[tid + i * 256] - mx);
        sl[tid + i * 256] = e;
        sum += e;
    }
    red[tid] = sum;
    __syncthreads();
    for (int s = 128; s > 0; s >>= 1) {
        if (tid < s) red[tid] += red[tid + s];
        __syncthreads();
    }
    const float inv = 1.0f / red[0];
    __syncthreads();

    #pragma unroll
    for (int i = 0; i < 4; i++)
        alphas_out[b * TT + tid + i * 256] = sl[tid + i * 256] * inv;
}

// ================= Kernel D1: weighted-sum partials (T split 8-ways) =================
__global__ __launch_bounds__(128) void wsum_part(
    const float* __restrict__ smiles,
    const float* __restrict__ alphas)
{
    __shared__ float al[128];
    const int tid = threadIdx.x;
    const int b   = blockIdx.x;
    const int c   = blockIdx.y;

    al[tid] = alphas[b * TT + c * 128 + tid];
    __syncthreads();

    const float4* sp = reinterpret_cast<const float4*>(
        smiles + ((size_t)b * TT + (size_t)c * 128) * HH) + tid;

    float4 a0 = {0,0,0,0}, a1 = {0,0,0,0}, a2 = {0,0,0,0}, a3 = {0,0,0,0};
    #pragma unroll
    for (int t = 0; t < 128; t += 8) {
        float4 s0 = sp[(size_t)(t + 0) * 128];
        float4 s1 = sp[(size_t)(t + 1) * 128];
        float4 s2 = sp[(size_t)(t + 2) * 128];
        float4 s3 = sp[(size_t)(t + 3) * 128];
        float4 s4 = sp[(size_t)(t + 4) * 128];
        float4 s5 = sp[(size_t)(t + 5) * 128];
        float4 s6 = sp[(size_t)(t + 6) * 128];
        float4 s7 = sp[(size_t)(t + 7) * 128];
        float w0 = al[t],     w1 = al[t + 1], w2 = al[t + 2], w3 = al[t + 3];
        float w4 = al[t + 4], w5 = al[t + 5], w6 = al[t + 6], w7 = al[t + 7];
        a0.x = fmaf(s0.x, w0, a0.x); a0.y = fmaf(s0.y, w0, a0.y);
        a0.z = fmaf(s0.z, w0, a0.z); a0.w = fmaf(s0.w, w0, a0.w);
        a1.x = fmaf(s1.x, w1, a1.x); a1.y = fmaf(s1.y, w1, a1.y);
        a1.z = fmaf(s1.z, w1, a1.z); a1.w = fmaf(s1.w, w1, a1.w);
        a2.x = fmaf(s2.x, w2, a2.x); a2.y = fmaf(s2.y, w2, a2.y);
        a2.z = fmaf(s2.z, w2, a2.z); a2.w = fmaf(s2.w, w2, a2.w);
        a3.x = fmaf(s3.x, w3, a3.x); a3.y = fmaf(s3.y, w3, a3.y);
        a3.z = fmaf(s3.z, w3, a3.z); a3.w = fmaf(s3.w, w3, a3.w);
        a0.x = fmaf(s4.x, w4, a0.x); a0.y = fmaf(s4.y, w4, a0.y);
        a0.z = fmaf(s4.z, w4, a0.z); a0.w = fmaf(s4.w, w4, a0.w);
        a1.x = fmaf(s5.x, w5, a1.x); a1.y = fmaf(s5.y, w5, a1.y);
        a1.z = fmaf(s5.z, w5, a1.z); a1.w = fmaf(s5.w, w5, a1.w);
        a2.x = fmaf(s6.x, w6, a2.x); a2.y = fmaf(s6.y, w6, a2.y);
        a2.z = fmaf(s6.z, w6, a2.z); a2.w = fmaf(s6.w, w6, a2.w);
        a3.x = fmaf(s7.x, w7, a3.x); a3.y = fmaf(s7.y, w7, a3.y);
        a3.z = fmaf(s7.z, w7, a3.z); a3.w = fmaf(s7.w, w7, a3.w);
    }
    float4 out;
    out.x = (a0.x + a1.x) + (a2.x + a3.x);
    out.y = (a0.y + a1.y) + (a2.y + a3.y);
    out.z = (a0.z + a1.z) + (a2.z + a3.z);
    out.w = (a0.w + a1.w) + (a2.w + a3.w);
    *reinterpret_cast<float4*>(&g_part[((size_t)c * BB + b) * HH + tid * 4]) = out;
}

// ================= Kernel D2: reduce partials =================
__global__ __launch_bounds__(256) void wsum_reduce(float* __restrict__ out)
{
    const int i = blockIdx.x * 256 + threadIdx.x;
    float s = 0.f;
    #pragma unroll
    for (int c = 0; c < WS_SPLIT; c++) s += g_part[(size_t)c * BB * HH + i];
    out[i] = s;
}

// ================= launch =================
extern "C" void kernel_launch(void* const* d_in, const int* in_sizes, int n_in,
                              void* d_out, int out_size)
{
    const float* genes   = (const float*)d_in[0];   // [B, G]
    const float* smiles  = (const float*)d_in[1];   // [B, T, H]
    const float* w_num   = (const float*)d_in[2];   // [1]
    const float* w_genes = (const float*)d_in[3];   // [G, A]
    const float* b_genes = (const float*)d_in[4];   // [A]
    const float* dkernel = (const float*)d_in[5];   // [H, A]
    const float* dbias   = (const float*)d_in[6];   // [A]
    const float* vvec    = (const float*)d_in[7];   // [A]

    float* out    = (float*)d_out;                  // [B, H] at offset 0
    float* alphas = out + BB * HH;                  // [B, T] after output

    cudaFuncSetAttribute(attn_logits_f16k, cudaFuncAttributeMaxDynamicSharedMemorySize, 65536);

    gene_proj_part<<<dim3(32, 8), 256>>>(genes, w_genes);
    gene_proj_reduce<<<BB, 256>>>(w_num, b_genes);
    prep_bhalf<<<NSTAGE, 256>>>(dkernel);
    attn_logits_f16k<<<dim3(TT / 128, BB), 512, 65536>>>(smiles, dbias, vvec);
    softmax_kernel<<<BB, 256>>>(alphas);
    wsum_part<<<dim3(BB, WS_SPLIT), 128>>>(smiles, alphas);
    wsum_reduce<<<BB * HH / 256, 256>>>(out);
}